// round 2
// baseline (speedup 1.0000x reference)
#include <cuda_runtime.h>
#include <math.h>

#define N_NODES 4096
#define F_IN    256
#define C_TOT   256   // HEADS * F_OUT
#define HEADS   4
#define F_OUT   64

// Scratch (device globals: no allocation allowed in kernel_launch)
__device__ float g_h [N_NODES * C_TOT];     // 4 MB, h = x@W, layout [n][h*64+f]
__device__ float g_P1[N_NODES * HEADS];     // exp(e_i)
__device__ float g_P2[N_NODES * HEADS];     // exp(0.2*e_i)
__device__ float g_Q1[N_NODES * HEADS];     // exp(e_j)
__device__ float g_Q2[N_NODES * HEADS];     // exp(0.2*e_j)

// ---------------------------------------------------------------------------
// K1: h = x @ W   (4096x256 @ 256x256, fp32)
// 64x64 block tile, BK=16, 256 threads, 4x4 per thread.
// ---------------------------------------------------------------------------
__global__ __launch_bounds__(256) void k_gemm(const float* __restrict__ x,
                                              const float* __restrict__ W) {
    __shared__ __align__(16) float As[16][64];   // [k][m]
    __shared__ __align__(16) float Bs[16][64];   // [k][n]
    const int t  = threadIdx.x;
    const int n0 = blockIdx.x * 64;   // output col block
    const int m0 = blockIdx.y * 64;   // output row block
    const int tx = t & 15, ty = t >> 4;

    float acc[4][4];
#pragma unroll
    for (int i = 0; i < 4; ++i)
#pragma unroll
        for (int j = 0; j < 4; ++j) acc[i][j] = 0.f;

    for (int k0 = 0; k0 < F_IN; k0 += 16) {
        {   // A tile: 64 rows x 16 k  (one float4 per thread), store transposed
            int row = t >> 2, k4 = (t & 3) * 4;
            float4 v = *(const float4*)&x[(m0 + row) * F_IN + k0 + k4];
            As[k4 + 0][row] = v.x; As[k4 + 1][row] = v.y;
            As[k4 + 2][row] = v.z; As[k4 + 3][row] = v.w;
        }
        {   // B tile: 16 k x 64 cols (one float4 per thread)
            int krow = t >> 4, n4 = (t & 15) * 4;
            *(float4*)&Bs[krow][n4] = *(const float4*)&W[(k0 + krow) * C_TOT + n0 + n4];
        }
        __syncthreads();
#pragma unroll
        for (int kk = 0; kk < 16; ++kk) {
            float a[4], b[4];
            *(float4*)a = *(float4*)&As[kk][ty * 4];
            *(float4*)b = *(float4*)&Bs[kk][tx * 4];
#pragma unroll
            for (int i = 0; i < 4; ++i)
#pragma unroll
                for (int j = 0; j < 4; ++j) acc[i][j] += a[i] * b[j];
        }
        __syncthreads();
    }
#pragma unroll
    for (int i = 0; i < 4; ++i) {
        float4 v = make_float4(acc[i][0], acc[i][1], acc[i][2], acc[i][3]);
        *(float4*)&g_h[(m0 + ty * 4 + i) * C_TOT + n0 + tx * 4] = v;
    }
}

// ---------------------------------------------------------------------------
// K2: per (node, head): e_i = h.a1, e_j = h.a2; store exp tables.
// One warp per (n, h). 4096 blocks x 128 threads.
// ---------------------------------------------------------------------------
__global__ __launch_bounds__(128) void k_prep(const float* __restrict__ a) {
    const int n    = blockIdx.x;
    const int h    = threadIdx.x >> 5;
    const int lane = threadIdx.x & 31;
    const float* base = g_h + n * C_TOT + h * F_OUT;

    float hv0 = base[lane], hv1 = base[lane + 32];
    float ei = hv0 * a[lane]      + hv1 * a[lane + 32];
    float ej = hv0 * a[64 + lane] + hv1 * a[96 + lane];
#pragma unroll
    for (int off = 16; off; off >>= 1) {
        ei += __shfl_down_sync(0xffffffffu, ei, off);
        ej += __shfl_down_sync(0xffffffffu, ej, off);
    }
    if (lane == 0) {
        int idx = n * HEADS + h;
        g_P1[idx] = expf(ei);
        g_P2[idx] = expf(0.2f * ei);
        g_Q1[idx] = expf(ej);
        g_Q2[idx] = expf(0.2f * ej);
    }
}

// ---------------------------------------------------------------------------
// K3: flash-style masked-softmax aggregation + head-mean.
//   w[i,j,h] = adj[i,j] ? max(P1[i,h]*Q1[j,h], P2[i,h]*Q2[j,h]) : 0
//   out[i,f] = 0.25 * sum_h ( sum_j w*h[j,h,f] ) / ( sum_j w )
// Block: 8 rows i, 256 threads; j-chunks of 32.
// Thread roles: phase2 builds w into smem (t -> jj=t>>3, ii=t&7);
//               phase3 accumulates (t -> jgroup=t>>7, h=(t>>5)&3, fpair=t&31).
// ---------------------------------------------------------------------------
#define TI 8
#define TJ 32

__global__ __launch_bounds__(256) void k_aggr(const int* __restrict__ adj,
                                              float* __restrict__ out) {
    __shared__ __align__(16) float hs[TJ * C_TOT];        // 32 KB (reused as accsm)
    __shared__ __align__(16) float ws[HEADS * TJ * TI];   // 4 KB  (reused as dred)
    __shared__ int   as_adj[TI * TJ];
    __shared__ float qs1[TJ * HEADS], qs2[TJ * HEADS];
    __shared__ float ps1[TI * HEADS], ps2[TI * HEADS];
    __shared__ float den_s[TI * HEADS];

    const int t  = threadIdx.x;
    const int i0 = blockIdx.x * TI;

    if (t < TI * HEADS) {
        ps1[t] = g_P1[i0 * HEADS + t];
        ps2[t] = g_P2[i0 * HEADS + t];
    }

    // phase-3 role
    const int g  = t >> 7;
    const int h  = (t >> 5) & 3;
    const int f2 = t & 31;
    const int c0 = h * F_OUT + f2 * 2;
    // phase-2 role
    const int jj2 = t >> 3;
    const int ii2 = t & 7;

    float acc[TI][2];
#pragma unroll
    for (int i = 0; i < TI; ++i) { acc[i][0] = 0.f; acc[i][1] = 0.f; }
    float dpriv[HEADS] = {0.f, 0.f, 0.f, 0.f};

    for (int j0 = 0; j0 < N_NODES; j0 += TJ) {
        __syncthreads();
        // ---- load phase ----
#pragma unroll
        for (int r = 0; r < 8; ++r) {
            int idx = t + r * 256;                 // 2048 float4 slots
            int jj = idx >> 6, c4 = (idx & 63) * 4;
            *(float4*)&hs[jj * C_TOT + c4] =
                *(const float4*)&g_h[(j0 + jj) * C_TOT + c4];
        }
        if (t < TJ * HEADS)            qs1[t] = g_Q1[j0 * HEADS + t];
        else if (t < 2 * TJ * HEADS)   { int u = t - TJ * HEADS; qs2[u] = g_Q2[j0 * HEADS + u]; }
        as_adj[t] = adj[(i0 + (t >> 5)) * N_NODES + j0 + (t & 31)];  // [ii][jj]
        __syncthreads();

        // ---- phase 2: build weights ----
        {
            int av = as_adj[ii2 * TJ + jj2];
#pragma unroll
            for (int h2 = 0; h2 < HEADS; ++h2) {
                float w = 0.f;
                if (av) w = fmaxf(ps1[ii2 * 4 + h2] * qs1[jj2 * 4 + h2],
                                  ps2[ii2 * 4 + h2] * qs2[jj2 * 4 + h2]);
                ws[(h2 * TJ + jj2) * TI + ii2] = w;
                dpriv[h2] += w;
            }
        }
        __syncthreads();

        // ---- phase 3: accumulate numerators ----
#pragma unroll
        for (int jj = g * 16; jj < g * 16 + 16; ++jj) {
            float2 hv = *(const float2*)&hs[jj * C_TOT + c0];
            float wv[8];
            *(float4*)&wv[0] = *(const float4*)&ws[(h * TJ + jj) * TI];
            *(float4*)&wv[4] = *(const float4*)&ws[(h * TJ + jj) * TI + 4];
#pragma unroll
            for (int ii = 0; ii < TI; ++ii) {
                acc[ii][0] += wv[ii] * hv.x;
                acc[ii][1] += wv[ii] * hv.y;
            }
        }
    }
    __syncthreads();

    // ---- merge + epilogue ----
    float* accsm = hs;   // 2*TI*C_TOT = 4096 floats <= 8192
    float* dred  = ws;   // TJ*TI*HEADS = 1024 floats
#pragma unroll
    for (int ii = 0; ii < TI; ++ii) {
        accsm[(g * TI + ii) * C_TOT + c0]     = acc[ii][0];
        accsm[(g * TI + ii) * C_TOT + c0 + 1] = acc[ii][1];
    }
#pragma unroll
    for (int h2 = 0; h2 < HEADS; ++h2)
        dred[(jj2 * TI + ii2) * HEADS + h2] = dpriv[h2];
    __syncthreads();

    if (t < TI * HEADS) {                 // t = ii*4 + h
        int ii = t >> 2, hh = t & 3;
        float d = 0.f;
        for (int jj = 0; jj < TJ; ++jj) d += dred[(jj * TI + ii) * HEADS + hh];
        den_s[t] = d;
    }
    __syncthreads();

    if (t < F_OUT) {
#pragma unroll
        for (int ii = 0; ii < TI; ++ii) {
            float v = 0.f;
#pragma unroll
            for (int hh = 0; hh < HEADS; ++hh) {
                float num = accsm[ii * C_TOT + hh * F_OUT + t]
                          + accsm[(TI + ii) * C_TOT + hh * F_OUT + t];
                v += num / den_s[ii * 4 + hh];
            }
            out[(i0 + ii) * F_OUT + t] = 0.25f * v;
        }
    }
}

// ---------------------------------------------------------------------------
extern "C" void kernel_launch(void* const* d_in, const int* in_sizes, int n_in,
                              void* d_out, int out_size) {
    const float* x   = (const float*)d_in[0];   // (4096, 256)
    const int*   adj = (const int*)  d_in[1];   // (4096, 4096)
    const float* W   = (const float*)d_in[2];   // (256, 256)
    const float* a   = (const float*)d_in[3];   // (128, 1)
    float* out = (float*)d_out;                 // (4096, 64)

    k_gemm<<<dim3(C_TOT / 64, N_NODES / 64), 256>>>(x, W);
    k_prep<<<N_NODES, 128>>>(a);
    k_aggr<<<N_NODES / TI, 256>>>(adj, out);
}

// round 3
// speedup vs baseline: 3.6465x; 3.6465x over previous
#include <cuda_runtime.h>
#include <math.h>

#define N_NODES 4096
#define F_IN    256
#define C_TOT   256   // HEADS * F_OUT
#define HEADS   4
#define F_OUT   64
#define JSPLIT  2
#define NWORDS  (N_NODES / 32)   // 128 mask words per row

// Scratch (device globals: no allocation allowed in kernel_launch)
__device__ float    g_h [N_NODES * C_TOT];          // 4 MB  h = x@W
__device__ float    g_P1[N_NODES * HEADS];          // exp(e_i)
__device__ float    g_P2[N_NODES * HEADS];          // exp(0.2 e_i)
__device__ float    g_Q1[N_NODES * HEADS];          // exp(e_j)
__device__ float    g_Q2[N_NODES * HEADS];          // exp(0.2 e_j)
__device__ unsigned g_adjm[N_NODES * NWORDS];       // 2 MB adj bitmask
__device__ float    g_part[JSPLIT * HEADS * N_NODES * F_OUT]; // 8 MB partial numerators
__device__ float    g_pden[JSPLIT * HEADS * N_NODES];         // partial denominators

// ---------------------------------------------------------------------------
// K1: h = x @ W   (4096x256 @ 256x256, fp32 SIMT; ~27us, not the bottleneck)
// ---------------------------------------------------------------------------
__global__ __launch_bounds__(256) void k_gemm(const float* __restrict__ x,
                                              const float* __restrict__ W) {
    __shared__ __align__(16) float As[16][64];
    __shared__ __align__(16) float Bs[16][64];
    const int t  = threadIdx.x;
    const int n0 = blockIdx.x * 64;
    const int m0 = blockIdx.y * 64;
    const int tx = t & 15, ty = t >> 4;

    float acc[4][4];
#pragma unroll
    for (int i = 0; i < 4; ++i)
#pragma unroll
        for (int j = 0; j < 4; ++j) acc[i][j] = 0.f;

    for (int k0 = 0; k0 < F_IN; k0 += 16) {
        {
            int row = t >> 2, k4 = (t & 3) * 4;
            float4 v = *(const float4*)&x[(m0 + row) * F_IN + k0 + k4];
            As[k4 + 0][row] = v.x; As[k4 + 1][row] = v.y;
            As[k4 + 2][row] = v.z; As[k4 + 3][row] = v.w;
        }
        {
            int krow = t >> 4, n4 = (t & 15) * 4;
            *(float4*)&Bs[krow][n4] = *(const float4*)&W[(k0 + krow) * C_TOT + n0 + n4];
        }
        __syncthreads();
#pragma unroll
        for (int kk = 0; kk < 16; ++kk) {
            float a[4], b[4];
            *(float4*)a = *(float4*)&As[kk][ty * 4];
            *(float4*)b = *(float4*)&Bs[kk][tx * 4];
#pragma unroll
            for (int i = 0; i < 4; ++i)
#pragma unroll
                for (int j = 0; j < 4; ++j) acc[i][j] += a[i] * b[j];
        }
        __syncthreads();
    }
#pragma unroll
    for (int i = 0; i < 4; ++i) {
        float4 v = make_float4(acc[i][0], acc[i][1], acc[i][2], acc[i][3]);
        *(float4*)&g_h[(m0 + ty * 4 + i) * C_TOT + n0 + tx * 4] = v;
    }
}

// ---------------------------------------------------------------------------
// K2: per (node, head): e_i = h.a1, e_j = h.a2; store exp tables.
// ---------------------------------------------------------------------------
__global__ __launch_bounds__(128) void k_prep(const float* __restrict__ a) {
    const int n    = blockIdx.x;
    const int h    = threadIdx.x >> 5;
    const int lane = threadIdx.x & 31;
    const float* base = g_h + n * C_TOT + h * F_OUT;

    float hv0 = base[lane], hv1 = base[lane + 32];
    float ei = hv0 * a[lane]      + hv1 * a[lane + 32];
    float ej = hv0 * a[64 + lane] + hv1 * a[96 + lane];
#pragma unroll
    for (int off = 16; off; off >>= 1) {
        ei += __shfl_down_sync(0xffffffffu, ei, off);
        ej += __shfl_down_sync(0xffffffffu, ej, off);
    }
    if (lane == 0) {
        int idx = n * HEADS + h;
        g_P1[idx] = expf(ei);
        g_P2[idx] = expf(0.2f * ei);
        g_Q1[idx] = expf(ej);
        g_Q2[idx] = expf(0.2f * ej);
    }
}

// ---------------------------------------------------------------------------
// K3a: pack adjacency to bitmask  (64 MB -> 2 MB)
// ---------------------------------------------------------------------------
__global__ __launch_bounds__(128) void k_pack(const int* __restrict__ adj) {
    const int i    = blockIdx.x;
    const int w    = threadIdx.x >> 5;
    const int lane = threadIdx.x & 31;
    const int* row = adj + (size_t)i * N_NODES;
#pragma unroll
    for (int wd = w; wd < NWORDS; wd += 4) {
        int v = row[wd * 32 + lane];
        unsigned m = __ballot_sync(0xffffffffu, v != 0);
        if (lane == 0) g_adjm[i * NWORDS + wd] = m;
    }
}

// ---------------------------------------------------------------------------
// K3b: tensor-core masked-softmax aggregation (tf32 mma.sync m16n8k8).
// Block = 64 i-rows x 1 head x 1 j-half. 4 warps, warp owns 16 rows x 64 f.
// A-fragment (weights) computed directly in registers from bitmask + exp
// tables; denominator accumulated from the SAME tf32-rounded values.
// ---------------------------------------------------------------------------
__device__ __forceinline__ void mma_tf32(float c[4],
                                         unsigned a0, unsigned a1,
                                         unsigned a2, unsigned a3,
                                         unsigned b0, unsigned b1) {
    asm volatile(
        "mma.sync.aligned.m16n8k8.row.col.f32.tf32.tf32.f32 "
        "{%0,%1,%2,%3}, {%4,%5,%6,%7}, {%8,%9}, {%0,%1,%2,%3};"
        : "+f"(c[0]), "+f"(c[1]), "+f"(c[2]), "+f"(c[3])
        : "r"(a0), "r"(a1), "r"(a2), "r"(a3), "r"(b0), "r"(b1));
}

__device__ __forceinline__ unsigned to_tf32(float x) {
    unsigned u;
    asm("cvt.rna.tf32.f32 %0, %1;" : "=r"(u) : "f"(x));
    return u;
}

#define HSTR 72   // smem stride (floats) -> conflict-free B-fragment LDS

__global__ __launch_bounds__(128) void k_aggr_mma() {
    __shared__ __align__(16) float  hs[64 * HSTR];   // 18 KB, H tile [j][f]
    __shared__ float2 qs[64];                        // (Q1, Q2) per j

    const int t    = threadIdx.x;
    const int w    = t >> 5;
    const int lane = t & 31;
    const int g    = lane >> 2;       // group id (row within m16 half)
    const int tg   = lane & 3;        // thread-in-group (k / col pos)
    const int head = blockIdx.y;
    const int js   = blockIdx.z;
    const int i0   = blockIdx.x * 64;
    const int row0 = i0 + w * 16 + g;
    const int row1 = row0 + 8;

    const float p1r0 = g_P1[row0 * HEADS + head], p2r0 = g_P2[row0 * HEADS + head];
    const float p1r1 = g_P1[row1 * HEADS + head], p2r1 = g_P2[row1 * HEADS + head];

    float acc[8][4];
#pragma unroll
    for (int nt = 0; nt < 8; ++nt)
#pragma unroll
        for (int k = 0; k < 4; ++k) acc[nt][k] = 0.f;
    float d0 = 0.f, d1 = 0.f;

    const unsigned* am0 = g_adjm + row0 * NWORDS;
    const unsigned* am1 = g_adjm + row1 * NWORDS;

    for (int c = 0; c < (N_NODES / JSPLIT) / 64; ++c) {
        const int j0 = js * (N_NODES / JSPLIT) + c * 64;
        const int wd = j0 >> 5;
        const unsigned m0a = am0[wd], m0b = am0[wd + 1];
        const unsigned m1a = am1[wd], m1b = am1[wd + 1];

        __syncthreads();
        // stage H tile (tf32-rounded) : 64 rows x 64 f
#pragma unroll
        for (int r = 0; r < 8; ++r) {
            int idx = t + r * 128;
            int jj = idx >> 4, f4 = (idx & 15) << 2;
            float4 v = *(const float4*)&g_h[(size_t)(j0 + jj) * C_TOT + head * F_OUT + f4];
            float4 o;
            o.x = __uint_as_float(to_tf32(v.x));
            o.y = __uint_as_float(to_tf32(v.y));
            o.z = __uint_as_float(to_tf32(v.z));
            o.w = __uint_as_float(to_tf32(v.w));
            *(float4*)&hs[jj * HSTR + f4] = o;
        }
        if (t < 64)
            qs[t] = make_float2(g_Q1[(j0 + t) * HEADS + head],
                                g_Q2[(j0 + t) * HEADS + head]);
        __syncthreads();

#pragma unroll
        for (int kk = 0; kk < 8; ++kk) {
            const unsigned w0 = (kk < 4) ? m0a : m0b;
            const unsigned w1 = (kk < 4) ? m1a : m1b;
            const int sl   = (kk * 8) & 31;
            const int j_lo = kk * 8 + tg;
            const int j_hi = j_lo + 4;
            const float2 qlo = qs[j_lo];
            const float2 qhi = qs[j_hi];

            float v00 = fmaxf(p1r0 * qlo.x, p2r0 * qlo.y);
            float v10 = fmaxf(p1r1 * qlo.x, p2r1 * qlo.y);
            float v01 = fmaxf(p1r0 * qhi.x, p2r0 * qhi.y);
            float v11 = fmaxf(p1r1 * qhi.x, p2r1 * qhi.y);
            float a00 = ((w0 >> (sl + tg))     & 1u) ? v00 : 0.f;
            float a10 = ((w1 >> (sl + tg))     & 1u) ? v10 : 0.f;
            float a01 = ((w0 >> (sl + tg + 4)) & 1u) ? v01 : 0.f;
            float a11 = ((w1 >> (sl + tg + 4)) & 1u) ? v11 : 0.f;

            unsigned ua0 = to_tf32(a00);
            unsigned ua1 = to_tf32(a10);
            unsigned ua2 = to_tf32(a01);
            unsigned ua3 = to_tf32(a11);
            d0 += __uint_as_float(ua0) + __uint_as_float(ua2);
            d1 += __uint_as_float(ua1) + __uint_as_float(ua3);

            const float* blo = &hs[j_lo * HSTR + g];
            const float* bhi = &hs[j_hi * HSTR + g];
#pragma unroll
            for (int nt = 0; nt < 8; ++nt) {
                unsigned b0 = __float_as_uint(blo[nt * 8]);
                unsigned b1 = __float_as_uint(bhi[nt * 8]);
                mma_tf32(acc[nt], ua0, ua1, ua2, ua3, b0, b1);
            }
        }
    }

    // epilogue: quad-reduce denominators, write partials
    d0 += __shfl_xor_sync(0xffffffffu, d0, 1);
    d0 += __shfl_xor_sync(0xffffffffu, d0, 2);
    d1 += __shfl_xor_sync(0xffffffffu, d1, 1);
    d1 += __shfl_xor_sync(0xffffffffu, d1, 2);

    const size_t pb = (size_t)(js * HEADS + head) * N_NODES;
    if (tg == 0) {
        g_pden[pb + row0] = d0;
        g_pden[pb + row1] = d1;
    }
    float* p0 = &g_part[(pb + row0) * F_OUT];
    float* p1 = &g_part[(pb + row1) * F_OUT];
#pragma unroll
    for (int nt = 0; nt < 8; ++nt) {
        *(float2*)&p0[nt * 8 + tg * 2] = make_float2(acc[nt][0], acc[nt][1]);
        *(float2*)&p1[nt * 8 + tg * 2] = make_float2(acc[nt][2], acc[nt][3]);
    }
}

// ---------------------------------------------------------------------------
// K4: combine partials: out[i,f] = 0.25 * sum_h (num0+num1)/(den0+den1)
// ---------------------------------------------------------------------------
__global__ __launch_bounds__(256) void k_combine(float* __restrict__ out) {
    const int t = blockIdx.x * 256 + threadIdx.x;    // 0 .. 4096*64-1
    const int i = t >> 6;
    const int f = t & 63;
    float v = 0.f;
#pragma unroll
    for (int h = 0; h < HEADS; ++h) {
        float num = g_part[((size_t)h * N_NODES + i) * F_OUT + f]
                  + g_part[((size_t)(HEADS + h) * N_NODES + i) * F_OUT + f];
        float den = g_pden[(size_t)h * N_NODES + i]
                  + g_pden[(size_t)(HEADS + h) * N_NODES + i];
        v += num / den;
    }
    out[t] = 0.25f * v;
}

// ---------------------------------------------------------------------------
extern "C" void kernel_launch(void* const* d_in, const int* in_sizes, int n_in,
                              void* d_out, int out_size) {
    const float* x   = (const float*)d_in[0];   // (4096, 256)
    const int*   adj = (const int*)  d_in[1];   // (4096, 4096)
    const float* W   = (const float*)d_in[2];   // (256, 256)
    const float* a   = (const float*)d_in[3];   // (128, 1)
    float* out = (float*)d_out;                 // (4096, 64)

    k_gemm<<<dim3(C_TOT / 64, N_NODES / 64), 256>>>(x, W);
    k_prep<<<N_NODES, 128>>>(a);
    k_pack<<<N_NODES, 128>>>(adj);
    k_aggr_mma<<<dim3(N_NODES / 64, HEADS, JSPLIT), 128>>>();
    k_combine<<<(N_NODES * F_OUT) / 256, 256>>>(out);
}